// round 9
// baseline (speedup 1.0000x reference)
#include <cuda_runtime.h>
#include <cuda_bf16.h>
#include <cstdint>

namespace {
constexpr float SCALE = 0.17677669529663687f;                 // 32^-0.5
// attn smem byte offsets. bf16 rows: 72 elems = 144 B (16-byte aligned; 144
// mod 128 = 16 so ldmatrix 8-row sets hit distinct bank quads — R8-verified).
constexpr int QS  = 0;                    // [256][72] bf16  (hi cols 0-31, lo 32-63)
constexpr int VS  = 36864;                // [256][72] bf16
constexpr int KC  = 73728;                // 2 x [64][72] bf16 (double-buffered chunks)
constexpr int WT  = 92160;                // [9][32] fp32
constexpr int BSO = 93312;                // [32] fp32
constexpr int SMEM_SZ = 93440;
}

// bf16 hi|lo windowed scratch, attn-smem-image layout: [s][((win*8+head)*256+t)*72]
__device__ __align__(16) unsigned short g_bf[3][(size_t)262144 * 72];
__device__ float g_oscr[8388608];          // out windowed [win][head][t][d] fp32

__device__ __forceinline__ void split_bf(float x, uint32_t& h, uint32_t& l) {
    __nv_bfloat16 bh = __float2bfloat16(x);
    __nv_bfloat16 bl = __float2bfloat16(x - __bfloat162float(bh));
    h = (uint32_t)__bfloat16_as_ushort(bh);
    l = (uint32_t)__bfloat16_as_ushort(bl);
}
__device__ __forceinline__ uint32_t pkbf(float lo, float hi) {
    uint32_t r;
    asm("cvt.rn.bf16x2.f32 %0, %1, %2;" : "=r"(r) : "f"(hi), "f"(lo));
    return r;
}
__device__ __forceinline__ void ldsm4(uint32_t& r0, uint32_t& r1, uint32_t& r2, uint32_t& r3, uint32_t a) {
    asm volatile("ldmatrix.sync.aligned.m8n8.x4.shared.b16 {%0,%1,%2,%3}, [%4];"
        : "=r"(r0), "=r"(r1), "=r"(r2), "=r"(r3) : "r"(a));
}
__device__ __forceinline__ void ldsm4t(uint32_t& r0, uint32_t& r1, uint32_t& r2, uint32_t& r3, uint32_t a) {
    asm volatile("ldmatrix.sync.aligned.m8n8.x4.trans.shared.b16 {%0,%1,%2,%3}, [%4];"
        : "=r"(r0), "=r"(r1), "=r"(r2), "=r"(r3) : "r"(a));
}
__device__ __forceinline__ void mma16816(float* d, const uint32_t* a, uint32_t b0, uint32_t b1) {
    asm volatile("mma.sync.aligned.m16n8k16.row.col.f32.bf16.bf16.f32 "
        "{%0,%1,%2,%3}, {%4,%5,%6,%7}, {%8,%9}, {%0,%1,%2,%3};"
        : "+f"(d[0]), "+f"(d[1]), "+f"(d[2]), "+f"(d[3])
        : "r"(a[0]), "r"(a[1]), "r"(a[2]), "r"(a[3]), "r"(b0), "r"(b1));
}
__device__ __forceinline__ void cpa16(uint32_t dst, const void* src) {
    asm volatile("cp.async.cg.shared.global [%0], [%1], 16;" :: "r"(dst), "l"(src));
}
__device__ __forceinline__ void cpa4(uint32_t dst, const void* src) {
    asm volatile("cp.async.ca.shared.global [%0], [%1], 4;" :: "r"(dst), "l"(src));
}
#define CPA_COMMIT() asm volatile("cp.async.commit_group;" ::: "memory")
#define CPA_WAIT(n)  asm volatile("cp.async.wait_group %0;" :: "n"(n) : "memory")

// ---------------------------------------------------------------------------
// Kernel 1: repack temp -> bf16 hi|lo windowed scratch (attn smem image).
// Transpose core verified since R4; conversion absorbed into DRAM-bound time.
// ---------------------------------------------------------------------------
__global__ void __launch_bounds__(256) repack_kernel(const float* __restrict__ temp) {
    __shared__ float tile[64 * 33];
    int r = blockIdx.x;
    int h = r & 63; r >>= 6;
    int head = r & 7; r >>= 3;
    int s = r % 3, b = r / 3;
    int tid = threadIdx.x;
    const float* src = temp + ((size_t)((b * 3 + s) * 256 + head * 32)) * 4096 + h * 64;
    int c = tid >> 3, w0 = (tid & 7) * 8;
    const float4* p = (const float4*)(src + (size_t)c * 4096 + w0);
    float4 v0 = p[0], v1 = p[1];
    float vv[8] = {v0.x, v0.y, v0.z, v0.w, v1.x, v1.y, v1.z, v1.w};
#pragma unroll
    for (int j = 0; j < 8; j++) tile[(w0 + j) * 33 + c] = vv[j];
    __syncthreads();
    int w = tid >> 2, c8 = (tid & 3) * 8;
    float o[8];
#pragma unroll
    for (int j = 0; j < 8; j++) o[j] = tile[w * 33 + c8 + j];
    int ww = w & 15, wsp = w >> 4;
    int win = b * 16 + ww, t = h * 4 + wsp;
    float m = (s == 0) ? SCALE : 1.0f;
    uint32_t hh[8], ll[8];
#pragma unroll
    for (int j = 0; j < 8; j++) split_bf(o[j] * m, hh[j], ll[j]);
    unsigned short* row = &g_bf[s][((size_t)(win * 8 + head) * 256 + t) * 72];
    *(uint4*)(row + c8) = make_uint4(hh[0] | (hh[1] << 16), hh[2] | (hh[3] << 16),
                                     hh[4] | (hh[5] << 16), hh[6] | (hh[7] << 16));
    *(uint4*)(row + 32 + c8) = make_uint4(ll[0] | (ll[1] << 16), ll[2] | (ll[3] << 16),
                                          ll[4] | (ll[5] << 16), ll[6] | (ll[7] << 16));
}

// ---------------------------------------------------------------------------
// Kernel 2: HMMA attention + lepe. CTA = (win,head), 256 thr / 8 warps,
// 2 CTAs/SM. Warp owns 32 query rows (two 16-row blocks). K double-buffered
// via cp.async; Q/V persistent (V frags shared by both row blocks).
// ---------------------------------------------------------------------------
__global__ void __launch_bounds__(256, 2) attn_mma(const float* __restrict__ gw,
                                                   const float* __restrict__ gb) {
    extern __shared__ char sm8[];
    uint32_t smb = (uint32_t)__cvta_generic_to_shared(sm8);
    float* Wt = (float*)(sm8 + WT);
    float* Bs = (float*)(sm8 + BSO);

    int tid = threadIdx.x, lane = tid & 31, warp = tid >> 5;
    int bid = blockIdx.x;
    int ww = bid & 15, head = (bid >> 4) & 7, b = bid >> 7;
    int win = b * 16 + ww;

    const char* Qp = (const char*)&g_bf[0][(size_t)(win * 8 + head) * 256 * 72];
    const char* Kp = (const char*)&g_bf[1][(size_t)(win * 8 + head) * 256 * 72];
    const char* Vp = (const char*)&g_bf[2][(size_t)(win * 8 + head) * 256 * 72];

    // prologue pipeline: g0 = Q+V+Wt+Bs, g1 = K chunk0, g2 = K chunk1
    for (int i = tid; i < 2304; i += 256) cpa16(smb + QS + i * 16, Qp + i * 16);
    for (int i = tid; i < 2304; i += 256) cpa16(smb + VS + i * 16, Vp + i * 16);
    for (int i = tid; i < 288; i += 256) cpa4(smb + WT + i * 4, gw + (head * 32 + (i & 31)) * 9 + (i >> 5));
    if (tid < 32) cpa4(smb + BSO + tid * 4, gb + head * 32 + tid);
    CPA_COMMIT();
    for (int i = tid; i < 576; i += 256) cpa16(smb + KC + i * 16, Kp + i * 16);
    CPA_COMMIT();
    for (int i = tid; i < 576; i += 256) cpa16(smb + KC + 9216 + i * 16, Kp + 9216 + i * 16);
    CPA_COMMIT();
    CPA_WAIT(2);
    __syncthreads();     // Q, V, Wt, Bs resident

    float O[2][4][4];
#pragma unroll
    for (int rb = 0; rb < 2; rb++)
#pragma unroll
        for (int nj = 0; nj < 4; nj++) O[rb][nj][0] = O[rb][nj][1] = O[rb][nj][2] = O[rb][nj][3] = 0.f;
    float lr[2][2] = {{0.f, 0.f}, {0.f, 0.f}};

    for (int kb = 0; kb < 4; kb++) {
        CPA_WAIT(1);
        __syncthreads();                     // K chunk kb resident in buf kb&1
        uint32_t kbuf = smb + KC + (uint32_t)(kb & 1) * 9216;
        int keyb = kb * 64;
        uint32_t ap[2][4][4];

#pragma unroll
        for (int rb = 0; rb < 2; rb++) {
            int q0 = warp * 32 + rb * 16;
            uint32_t qh[2][4], ql[2][4];
#pragma unroll
            for (int kc = 0; kc < 2; kc++) {
                uint32_t a = smb + QS + (uint32_t)(q0 + (lane & 7) + ((lane >> 3) & 1) * 8) * 144
                           + (uint32_t)(kc * 16 + (lane >> 4) * 8) * 2;
                ldsm4(qh[kc][0], qh[kc][1], qh[kc][2], qh[kc][3], a);
                ldsm4(ql[kc][0], ql[kc][1], ql[kc][2], ql[kc][3], a + 64);
            }
#pragma unroll
            for (int j = 0; j < 8; j++) {
                uint32_t ka = kbuf + (uint32_t)(j * 8 + (lane & 7)) * 144 + (uint32_t)((lane >> 3) * 8) * 2;
                uint32_t r0, r1, r2, r3, s0, s1, s2, s3;
                ldsm4(r0, r1, r2, r3, ka);        // khi
                ldsm4(s0, s1, s2, s3, ka + 64);   // klo
                float a4[4] = {0.f, 0.f, 0.f, 0.f};
                mma16816(a4, qh[0], r0, r1);
                mma16816(a4, qh[1], r2, r3);
                mma16816(a4, ql[0], r0, r1);
                mma16816(a4, ql[1], r2, r3);
                mma16816(a4, qh[0], s0, s1);
                mma16816(a4, qh[1], s2, s3);
                float e0 = __expf(a4[0]), e1 = __expf(a4[1]);
                float e2 = __expf(a4[2]), e3 = __expf(a4[3]);
                lr[rb][0] += e0 + e1;
                lr[rb][1] += e2 + e3;
                ap[rb][j >> 1][(j & 1) * 2]     = pkbf(e0, e1);
                ap[rb][j >> 1][(j & 1) * 2 + 1] = pkbf(e2, e3);
            }
        }
        // O += P (vhi + vlo): V frags shared by both row blocks
#pragma unroll
        for (int nj = 0; nj < 4; nj++) {
#pragma unroll
            for (int cp = 0; cp < 2; cp++) {
                uint32_t va = smb + VS + (uint32_t)(keyb + cp * 32 + lane) * 144 + (uint32_t)(nj * 8) * 2;
                uint32_t r0, r1, r2, r3;
                ldsm4t(r0, r1, r2, r3, va);        // vhi
                mma16816(O[0][nj], ap[0][2 * cp],     r0, r1);
                mma16816(O[0][nj], ap[0][2 * cp + 1], r2, r3);
                mma16816(O[1][nj], ap[1][2 * cp],     r0, r1);
                mma16816(O[1][nj], ap[1][2 * cp + 1], r2, r3);
                ldsm4t(r0, r1, r2, r3, va + 64);   // vlo
                mma16816(O[0][nj], ap[0][2 * cp],     r0, r1);
                mma16816(O[0][nj], ap[0][2 * cp + 1], r2, r3);
                mma16816(O[1][nj], ap[1][2 * cp],     r0, r1);
                mma16816(O[1][nj], ap[1][2 * cp + 1], r2, r3);
            }
        }
        __syncthreads();                     // buf kb&1 free
        if (kb + 2 < 4) {
            for (int i = tid; i < 576; i += 256)
                cpa16(smb + KC + (uint32_t)(kb & 1) * 9216 + i * 16, Kp + (kb + 2) * 9216 + i * 16);
        }
        CPA_COMMIT();                        // uniform group count (may be empty)
    }

    // epilogue: normalize + lepe (v = hi + lo), store windowed fp32
    size_t obase = (size_t)(win * 8 + head) * (256 * 32);
#pragma unroll
    for (int rb = 0; rb < 2; rb++) {
        float l0 = lr[rb][0], l1 = lr[rb][1];
        l0 += __shfl_xor_sync(0xffffffffu, l0, 1);
        l0 += __shfl_xor_sync(0xffffffffu, l0, 2);
        l1 += __shfl_xor_sync(0xffffffffu, l1, 1);
        l1 += __shfl_xor_sync(0xffffffffu, l1, 2);
        float inv0 = 1.0f / l0, inv1 = 1.0f / l1;
        int q0 = warp * 32 + rb * 16;
        int r = lane >> 2, cp2 = (lane & 3) * 2;
        int t0 = q0 + r, t1 = t0 + 8;
#pragma unroll
        for (int nj = 0; nj < 4; nj++) {
            int d = nj * 8 + cp2;
#pragma unroll
            for (int q = 0; q < 2; q++) {
                int t = q ? t1 : t0;
                int h = t >> 2, ws = t & 3;
                float ax = Bs[d], ay = Bs[d + 1];
#pragma unroll
                for (int kh = 0; kh < 3; kh++) {
                    int hn = h + kh - 1;
                    if ((unsigned)hn < 64u) {
#pragma unroll
                        for (int kw = 0; kw < 3; kw++) {
                            int wn = ws + kw - 1;
                            if ((unsigned)wn < 4u) {
                                int tn = hn * 4 + wn;
                                uint32_t vh = *(const uint32_t*)(sm8 + VS + tn * 144 + d * 2);
                                uint32_t vl = *(const uint32_t*)(sm8 + VS + tn * 144 + 64 + d * 2);
                                float vx = __bfloat162float(__ushort_as_bfloat16((unsigned short)vh)) +
                                           __bfloat162float(__ushort_as_bfloat16((unsigned short)vl));
                                float vy = __bfloat162float(__ushort_as_bfloat16((unsigned short)(vh >> 16))) +
                                           __bfloat162float(__ushort_as_bfloat16((unsigned short)(vl >> 16)));
                                float2 wg = *(const float2*)(Wt + (kh * 3 + kw) * 32 + d);
                                ax = fmaf(vx, wg.x, ax);
                                ay = fmaf(vy, wg.y, ay);
                            }
                        }
                    }
                }
                float inv = q ? inv1 : inv0;
                float ox = O[rb][nj][q * 2], oy = O[rb][nj][q * 2 + 1];
                *(float2*)(g_oscr + obase + (size_t)t * 32 + d) =
                    make_float2(fmaf(ox, inv, ax), fmaf(oy, inv, ay));
            }
        }
    }
}

// Kernel 3: inverse repack g_oscr -> out (B,C,H,W).
__global__ void __launch_bounds__(256) unpack_kernel(float* __restrict__ out) {
    __shared__ float tile[64 * 33];
    int r = blockIdx.x;
    int h = r & 63; r >>= 6;
    int head = r & 7, b = r >> 3;
    int tid = threadIdx.x;
    int w = tid >> 2, c8 = (tid & 3) * 8;
    int ww = w & 15, wsp = w >> 4;
    int win = b * 16 + ww, t = h * 4 + wsp;
    const float* src = g_oscr + ((size_t)(win * 8 + head) * 256 + t) * 32 + c8;
    float4 a = ((const float4*)src)[0], bb = ((const float4*)src)[1];
    float vv[8] = {a.x, a.y, a.z, a.w, bb.x, bb.y, bb.z, bb.w};
#pragma unroll
    for (int j = 0; j < 8; j++) tile[w * 33 + c8 + j] = vv[j];
    __syncthreads();
    int c = tid >> 3, w0 = (tid & 7) * 8;
    float o[8];
#pragma unroll
    for (int j = 0; j < 8; j++) o[j] = tile[(w0 + j) * 33 + c];
    float* dst = out + ((size_t)(b * 256 + head * 32 + c)) * 4096 + h * 64 + w0;
    ((float4*)dst)[0] = make_float4(o[0], o[1], o[2], o[3]);
    ((float4*)dst)[1] = make_float4(o[4], o[5], o[6], o[7]);
}

extern "C" void kernel_launch(void* const* d_in, const int* in_sizes, int n_in,
                              void* d_out, int out_size) {
    const float* temp = (const float*)d_in[0];
    const float* gw = (const float*)d_in[1];
    const float* gb = (const float*)d_in[2];
    float* out = (float*)d_out;
    (void)in_sizes; (void)n_in; (void)out_size;

    cudaFuncSetAttribute(attn_mma, cudaFuncAttributeMaxDynamicSharedMemorySize, SMEM_SZ);
    repack_kernel<<<12288, 256>>>(temp);
    attn_mma<<<1024, 256, SMEM_SZ>>>(gw, gb);
    unpack_kernel<<<4096, 256>>>(out);
}

// round 10
// speedup vs baseline: 1.6814x; 1.6814x over previous
#include <cuda_runtime.h>
#include <cuda_fp16.h>
#include <cstdint>

namespace {
constexpr float SCALE = 0.17677669529663687f;                 // 32^-0.5
// attn smem. fp16 rows: 40 elems = 80 B. 8-row ldmatrix sets at stride 80 B
// hit word offsets {0,20,8,28,16,4,24,12}*4B -> all 32 banks covered, 0 conflicts.
constexpr int QS  = 0;                    // [256][40] fp16 (cols 0-31 data)
constexpr int VS  = 20480;                // [256][40] fp16
constexpr int KC  = 40960;                // 2 x [64][40] fp16 (double-buffered)
constexpr int WT  = 51200;                // [9][32] fp32
constexpr int BSO = 52352;                // [32] fp32
constexpr int SMEM_SZ = 52480;
}

// fp16 windowed scratch, attn-smem-image layout: [s][((win*8+head)*256+t)*40]
__device__ __align__(16) unsigned short g_half[3][(size_t)262144 * 40];
__device__ float g_oscr[8388608];          // out windowed [win][head][t][d] fp32

__device__ __forceinline__ uint32_t pkhf(float lo, float hi) {
    uint32_t r;
    asm("cvt.rn.f16x2.f32 %0, %1, %2;" : "=r"(r) : "f"(hi), "f"(lo));
    return r;
}
__device__ __forceinline__ void ldsm4(uint32_t& r0, uint32_t& r1, uint32_t& r2, uint32_t& r3, uint32_t a) {
    asm volatile("ldmatrix.sync.aligned.m8n8.x4.shared.b16 {%0,%1,%2,%3}, [%4];"
        : "=r"(r0), "=r"(r1), "=r"(r2), "=r"(r3) : "r"(a));
}
__device__ __forceinline__ void ldsm4t(uint32_t& r0, uint32_t& r1, uint32_t& r2, uint32_t& r3, uint32_t a) {
    asm volatile("ldmatrix.sync.aligned.m8n8.x4.trans.shared.b16 {%0,%1,%2,%3}, [%4];"
        : "=r"(r0), "=r"(r1), "=r"(r2), "=r"(r3) : "r"(a));
}
__device__ __forceinline__ void mma16816(float* d, const uint32_t* a, uint32_t b0, uint32_t b1) {
    asm volatile("mma.sync.aligned.m16n8k16.row.col.f32.f16.f16.f32 "
        "{%0,%1,%2,%3}, {%4,%5,%6,%7}, {%8,%9}, {%0,%1,%2,%3};"
        : "+f"(d[0]), "+f"(d[1]), "+f"(d[2]), "+f"(d[3])
        : "r"(a[0]), "r"(a[1]), "r"(a[2]), "r"(a[3]), "r"(b0), "r"(b1));
}
__device__ __forceinline__ void cpa16(uint32_t dst, const void* src) {
    asm volatile("cp.async.cg.shared.global [%0], [%1], 16;" :: "r"(dst), "l"(src));
}
__device__ __forceinline__ void cpa4(uint32_t dst, const void* src) {
    asm volatile("cp.async.ca.shared.global [%0], [%1], 4;" :: "r"(dst), "l"(src));
}
#define CPA_COMMIT() asm volatile("cp.async.commit_group;" ::: "memory")
#define CPA_WAIT(n)  asm volatile("cp.async.wait_group %0;" :: "n"(n) : "memory")

// ---------------------------------------------------------------------------
// Kernel 1: repack temp (B,3,C,H,W) fp32 -> fp16 windowed scratch.
// Transpose core verified since R4. Q pre-scaled by 32^-0.5.
// ---------------------------------------------------------------------------
__global__ void __launch_bounds__(256) repack_kernel(const float* __restrict__ temp) {
    __shared__ float tile[64 * 33];
    int r = blockIdx.x;
    int h = r & 63; r >>= 6;
    int head = r & 7; r >>= 3;
    int s = r % 3, b = r / 3;
    int tid = threadIdx.x;
    const float* src = temp + ((size_t)((b * 3 + s) * 256 + head * 32)) * 4096 + h * 64;
    int c = tid >> 3, w0 = (tid & 7) * 8;
    const float4* p = (const float4*)(src + (size_t)c * 4096 + w0);
    float4 v0 = p[0], v1 = p[1];
    float vv[8] = {v0.x, v0.y, v0.z, v0.w, v1.x, v1.y, v1.z, v1.w};
#pragma unroll
    for (int j = 0; j < 8; j++) tile[(w0 + j) * 33 + c] = vv[j];
    __syncthreads();
    int w = tid >> 2, c8 = (tid & 3) * 8;
    float o[8];
#pragma unroll
    for (int j = 0; j < 8; j++) o[j] = tile[w * 33 + c8 + j];
    int ww = w & 15, wsp = w >> 4;
    int win = b * 16 + ww, t = h * 4 + wsp;
    float m = (s == 0) ? SCALE : 1.0f;
    uint32_t pk[4];
#pragma unroll
    for (int j = 0; j < 4; j++) pk[j] = pkhf(o[2 * j] * m, o[2 * j + 1] * m);
    unsigned short* row = &g_half[s][((size_t)(win * 8 + head) * 256 + t) * 40];
    *(uint4*)(row + c8) = make_uint4(pk[0], pk[1], pk[2], pk[3]);
}

// ---------------------------------------------------------------------------
// Kernel 2: fp16 HMMA attention + lepe. CTA = (win,head), 256 thr / 8 warps,
// 2 CTAs/SM. Warp owns 32 query rows (two 16-row blocks); single-term fp16
// MMAs (error budget ~3e-4 < 1e-3). K double-buffered cp.async; Q frags
// hoisted; V frags shared across both row blocks.
// ---------------------------------------------------------------------------
__global__ void __launch_bounds__(256, 2) attn_mma(const float* __restrict__ gw,
                                                   const float* __restrict__ gb) {
    extern __shared__ char sm8[];
    uint32_t smb = (uint32_t)__cvta_generic_to_shared(sm8);
    float* Wt = (float*)(sm8 + WT);
    float* Bs = (float*)(sm8 + BSO);

    int tid = threadIdx.x, lane = tid & 31, warp = tid >> 5;
    int bid = blockIdx.x;
    int ww = bid & 15, head = (bid >> 4) & 7, b = bid >> 7;
    int win = b * 16 + ww;

    const char* Qp = (const char*)&g_half[0][(size_t)(win * 8 + head) * 256 * 40];
    const char* Kp = (const char*)&g_half[1][(size_t)(win * 8 + head) * 256 * 40];
    const char* Vp = (const char*)&g_half[2][(size_t)(win * 8 + head) * 256 * 40];

    // prologue: g0 = Q+V+Wt+Bs, g1 = K chunk0, g2 = K chunk1 (5120 B each)
#pragma unroll
    for (int it = 0; it < 5; it++) { int i = it * 256 + tid; cpa16(smb + QS + i * 16, Qp + i * 16); }
#pragma unroll
    for (int it = 0; it < 5; it++) { int i = it * 256 + tid; cpa16(smb + VS + i * 16, Vp + i * 16); }
    for (int i = tid; i < 288; i += 256) cpa4(smb + WT + i * 4, gw + (head * 32 + (i & 31)) * 9 + (i >> 5));
    if (tid < 32) cpa4(smb + BSO + tid * 4, gb + head * 32 + tid);
    CPA_COMMIT();
    for (int i = tid; i < 320; i += 256) cpa16(smb + KC + i * 16, Kp + i * 16);
    CPA_COMMIT();
    for (int i = tid; i < 320; i += 256) cpa16(smb + KC + 5120 + i * 16, Kp + 5120 + i * 16);
    CPA_COMMIT();
    CPA_WAIT(2);
    __syncthreads();     // Q, V, Wt, Bs resident

    // hoisted Q fragments: [rb][kc][4]
    uint32_t qf[2][2][4];
#pragma unroll
    for (int rb = 0; rb < 2; rb++)
#pragma unroll
        for (int kc = 0; kc < 2; kc++) {
            uint32_t a = smb + QS
                + (uint32_t)(warp * 32 + rb * 16 + (lane & 7) + ((lane >> 3) & 1) * 8) * 80
                + (uint32_t)(kc * 16 + (lane >> 4) * 8) * 2;
            ldsm4(qf[rb][kc][0], qf[rb][kc][1], qf[rb][kc][2], qf[rb][kc][3], a);
        }

    float O[2][4][4];
#pragma unroll
    for (int rb = 0; rb < 2; rb++)
#pragma unroll
        for (int nj = 0; nj < 4; nj++) O[rb][nj][0] = O[rb][nj][1] = O[rb][nj][2] = O[rb][nj][3] = 0.f;
    float lr[2][2] = {{0.f, 0.f}, {0.f, 0.f}};

    for (int kb = 0; kb < 4; kb++) {
        CPA_WAIT(1);
        __syncthreads();                     // K chunk kb resident in buf kb&1
        uint32_t kbuf = smb + KC + (uint32_t)(kb & 1) * 5120;
        int keyb = kb * 64;
        uint32_t ap[2][4][4];

#pragma unroll
        for (int rb = 0; rb < 2; rb++) {
#pragma unroll
            for (int j = 0; j < 8; j++) {
                uint32_t ka = kbuf + (uint32_t)(j * 8 + (lane & 7)) * 80 + (uint32_t)((lane >> 3) * 8) * 2;
                uint32_t r0, r1, r2, r3;
                ldsm4(r0, r1, r2, r3, ka);
                float a4[4] = {0.f, 0.f, 0.f, 0.f};
                mma16816(a4, qf[rb][0], r0, r1);
                mma16816(a4, qf[rb][1], r2, r3);
                float e0 = __expf(a4[0]), e1 = __expf(a4[1]);
                float e2 = __expf(a4[2]), e3 = __expf(a4[3]);
                lr[rb][0] += e0 + e1;
                lr[rb][1] += e2 + e3;
                ap[rb][j >> 1][(j & 1) * 2]     = pkhf(e0, e1);
                ap[rb][j >> 1][(j & 1) * 2 + 1] = pkhf(e2, e3);
            }
        }
        // O += P V (V frags shared by both row blocks)
#pragma unroll
        for (int nj = 0; nj < 4; nj++) {
#pragma unroll
            for (int cp = 0; cp < 2; cp++) {
                uint32_t va = smb + VS + (uint32_t)(keyb + cp * 32 + lane) * 80 + (uint32_t)(nj * 8) * 2;
                uint32_t r0, r1, r2, r3;
                ldsm4t(r0, r1, r2, r3, va);
                mma16816(O[0][nj], ap[0][2 * cp],     r0, r1);
                mma16816(O[0][nj], ap[0][2 * cp + 1], r2, r3);
                mma16816(O[1][nj], ap[1][2 * cp],     r0, r1);
                mma16816(O[1][nj], ap[1][2 * cp + 1], r2, r3);
            }
        }
        __syncthreads();                     // buf kb&1 free
        if (kb + 2 < 4) {
            for (int i = tid; i < 320; i += 256)
                cpa16(smb + KC + (uint32_t)(kb & 1) * 5120 + i * 16, Kp + (kb + 2) * 5120 + i * 16);
        }
        CPA_COMMIT();                        // uniform group count
    }

    // epilogue: normalize + lepe (fp16 v), store windowed fp32
    size_t obase = (size_t)(win * 8 + head) * (256 * 32);
#pragma unroll
    for (int rb = 0; rb < 2; rb++) {
        float l0 = lr[rb][0], l1 = lr[rb][1];
        l0 += __shfl_xor_sync(0xffffffffu, l0, 1);
        l0 += __shfl_xor_sync(0xffffffffu, l0, 2);
        l1 += __shfl_xor_sync(0xffffffffu, l1, 1);
        l1 += __shfl_xor_sync(0xffffffffu, l1, 2);
        float inv0 = 1.0f / l0, inv1 = 1.0f / l1;
        int q0 = warp * 32 + rb * 16;
        int r = lane >> 2, cp2 = (lane & 3) * 2;
        int t0 = q0 + r, t1 = t0 + 8;
#pragma unroll
        for (int nj = 0; nj < 4; nj++) {
            int d = nj * 8 + cp2;
#pragma unroll
            for (int q = 0; q < 2; q++) {
                int t = q ? t1 : t0;
                int h = t >> 2, ws = t & 3;
                float ax = Bs[d], ay = Bs[d + 1];
#pragma unroll
                for (int kh = 0; kh < 3; kh++) {
                    int hn = h + kh - 1;
                    if ((unsigned)hn < 64u) {
#pragma unroll
                        for (int kw = 0; kw < 3; kw++) {
                            int wn = ws + kw - 1;
                            if ((unsigned)wn < 4u) {
                                int tn = hn * 4 + wn;
                                uint32_t vp = *(const uint32_t*)(sm8 + VS + tn * 80 + d * 2);
                                float vx = __half2float(__ushort_as_half((unsigned short)vp));
                                float vy = __half2float(__ushort_as_half((unsigned short)(vp >> 16)));
                                float2 wg = *(const float2*)(Wt + (kh * 3 + kw) * 32 + d);
                                ax = fmaf(vx, wg.x, ax);
                                ay = fmaf(vy, wg.y, ay);
                            }
                        }
                    }
                }
                float inv = q ? inv1 : inv0;
                float ox = O[rb][nj][q * 2], oy = O[rb][nj][q * 2 + 1];
                *(float2*)(g_oscr + obase + (size_t)t * 32 + d) =
                    make_float2(fmaf(ox, inv, ax), fmaf(oy, inv, ay));
            }
        }
    }
}

// Kernel 3: inverse repack g_oscr -> out (B,C,H,W).
__global__ void __launch_bounds__(256) unpack_kernel(float* __restrict__ out) {
    __shared__ float tile[64 * 33];
    int r = blockIdx.x;
    int h = r & 63; r >>= 6;
    int head = r & 7, b = r >> 3;
    int tid = threadIdx.x;
    int w = tid >> 2, c8 = (tid & 3) * 8;
    int ww = w & 15, wsp = w >> 4;
    int win = b * 16 + ww, t = h * 4 + wsp;
    const float* src = g_oscr + ((size_t)(win * 8 + head) * 256 + t) * 32 + c8;
    float4 a = ((const float4*)src)[0], bb = ((const float4*)src)[1];
    float vv[8] = {a.x, a.y, a.z, a.w, bb.x, bb.y, bb.z, bb.w};
#pragma unroll
    for (int j = 0; j < 8; j++) tile[w * 33 + c8 + j] = vv[j];
    __syncthreads();
    int c = tid >> 3, w0 = (tid & 7) * 8;
    float o[8];
#pragma unroll
    for (int j = 0; j < 8; j++) o[j] = tile[(w0 + j) * 33 + c];
    float* dst = out + ((size_t)(b * 256 + head * 32 + c)) * 4096 + h * 64 + w0;
    ((float4*)dst)[0] = make_float4(o[0], o[1], o[2], o[3]);
    ((float4*)dst)[1] = make_float4(o[4], o[5], o[6], o[7]);
}

extern "C" void kernel_launch(void* const* d_in, const int* in_sizes, int n_in,
                              void* d_out, int out_size) {
    const float* temp = (const float*)d_in[0];
    const float* gw = (const float*)d_in[1];
    const float* gb = (const float*)d_in[2];
    float* out = (float*)d_out;
    (void)in_sizes; (void)n_in; (void)out_size;

    cudaFuncSetAttribute(attn_mma, cudaFuncAttributeMaxDynamicSharedMemorySize, SMEM_SZ);
    repack_kernel<<<12288, 256>>>(temp);
    attn_mma<<<1024, 256, SMEM_SZ>>>(gw, gb);
    unpack_kernel<<<4096, 256>>>(out);
}

// round 11
// speedup vs baseline: 1.7209x; 1.0235x over previous
#include <cuda_runtime.h>
#include <cuda_fp16.h>
#include <cstdint>

namespace {
constexpr float SCALE = 0.17677669529663687f;                 // 32^-0.5
// attn smem. fp16 rows: 40 elems = 80 B. 8-row ldmatrix sets at stride 80 B
// hit word offsets {0,20,8,28,16,4,24,12}*4B -> all 32 banks, 0 conflicts.
constexpr int QS  = 0;                    // [256][40] fp16 (cols 0-31 data)
constexpr int KS  = 20480;                // [256][40] fp16 (ALL of K resident)
constexpr int VS  = 40960;                // [256][40] fp16
constexpr int WT  = 61440;                // [9][32] fp32
constexpr int BSO = 62592;                // [32] fp32
constexpr int SMEM_SZ = 62720;
}

// fp16 windowed scratch, attn-smem-image layout: [s][((win*8+head)*256+t)*40]
__device__ __align__(16) unsigned short g_half[3][(size_t)262144 * 40];
__device__ float g_oscr[8388608];          // out windowed [win][head][t][d] fp32

__device__ __forceinline__ uint32_t pkhf(float lo, float hi) {
    uint32_t r;
    asm("cvt.rn.f16x2.f32 %0, %1, %2;" : "=r"(r) : "f"(hi), "f"(lo));
    return r;
}
__device__ __forceinline__ void ldsm4(uint32_t& r0, uint32_t& r1, uint32_t& r2, uint32_t& r3, uint32_t a) {
    asm volatile("ldmatrix.sync.aligned.m8n8.x4.shared.b16 {%0,%1,%2,%3}, [%4];"
        : "=r"(r0), "=r"(r1), "=r"(r2), "=r"(r3) : "r"(a));
}
__device__ __forceinline__ void ldsm4t(uint32_t& r0, uint32_t& r1, uint32_t& r2, uint32_t& r3, uint32_t a) {
    asm volatile("ldmatrix.sync.aligned.m8n8.x4.trans.shared.b16 {%0,%1,%2,%3}, [%4];"
        : "=r"(r0), "=r"(r1), "=r"(r2), "=r"(r3) : "r"(a));
}
__device__ __forceinline__ void mma16816(float* d, const uint32_t* a, uint32_t b0, uint32_t b1) {
    asm volatile("mma.sync.aligned.m16n8k16.row.col.f32.f16.f16.f32 "
        "{%0,%1,%2,%3}, {%4,%5,%6,%7}, {%8,%9}, {%0,%1,%2,%3};"
        : "+f"(d[0]), "+f"(d[1]), "+f"(d[2]), "+f"(d[3])
        : "r"(a[0]), "r"(a[1]), "r"(a[2]), "r"(a[3]), "r"(b0), "r"(b1));
}
__device__ __forceinline__ void cpa16(uint32_t dst, const void* src) {
    asm volatile("cp.async.cg.shared.global [%0], [%1], 16;" :: "r"(dst), "l"(src));
}
__device__ __forceinline__ void cpa4(uint32_t dst, const void* src) {
    asm volatile("cp.async.ca.shared.global [%0], [%1], 4;" :: "r"(dst), "l"(src));
}
#define CPA_COMMIT() asm volatile("cp.async.commit_group;" ::: "memory")
#define CPA_WAIT(n)  asm volatile("cp.async.wait_group %0;" :: "n"(n) : "memory")

// ---------------------------------------------------------------------------
// Kernel 1: repack temp (B,3,C,H,W) fp32 -> fp16 windowed scratch.
// Transpose core verified since R4. Q pre-scaled by 32^-0.5.
// ---------------------------------------------------------------------------
__global__ void __launch_bounds__(256) repack_kernel(const float* __restrict__ temp) {
    __shared__ float tile[64 * 33];
    int r = blockIdx.x;
    int h = r & 63; r >>= 6;
    int head = r & 7; r >>= 3;
    int s = r % 3, b = r / 3;
    int tid = threadIdx.x;
    const float* src = temp + ((size_t)((b * 3 + s) * 256 + head * 32)) * 4096 + h * 64;
    int c = tid >> 3, w0 = (tid & 7) * 8;
    const float4* p = (const float4*)(src + (size_t)c * 4096 + w0);
    float4 v0 = p[0], v1 = p[1];
    float vv[8] = {v0.x, v0.y, v0.z, v0.w, v1.x, v1.y, v1.z, v1.w};
#pragma unroll
    for (int j = 0; j < 8; j++) tile[(w0 + j) * 33 + c] = vv[j];
    __syncthreads();
    int w = tid >> 2, c8 = (tid & 3) * 8;
    float o[8];
#pragma unroll
    for (int j = 0; j < 8; j++) o[j] = tile[w * 33 + c8 + j];
    int ww = w & 15, wsp = w >> 4;
    int win = b * 16 + ww, t = h * 4 + wsp;
    float m = (s == 0) ? SCALE : 1.0f;
    uint32_t pk[4];
#pragma unroll
    for (int j = 0; j < 4; j++) pk[j] = pkhf(o[2 * j] * m, o[2 * j + 1] * m);
    unsigned short* row = &g_half[s][((size_t)(win * 8 + head) * 256 + t) * 40];
    *(uint4*)(row + c8) = make_uint4(pk[0], pk[1], pk[2], pk[3]);
}

// ---------------------------------------------------------------------------
// Kernel 2: fp16 HMMA attention + lepe. CTA = (win,head), 256 thr / 8 warps,
// 2 CTAs/SM. ALL of Q/K/V resident in smem after one prologue wait; zero
// block syncs in the compute phase — warps fully independent.
// ---------------------------------------------------------------------------
__global__ void __launch_bounds__(256, 2) attn_mma(const float* __restrict__ gw,
                                                   const float* __restrict__ gb) {
    extern __shared__ char sm8[];
    uint32_t smb = (uint32_t)__cvta_generic_to_shared(sm8);
    float* Wt = (float*)(sm8 + WT);
    float* Bs = (float*)(sm8 + BSO);

    int tid = threadIdx.x, lane = tid & 31, warp = tid >> 5;
    int bid = blockIdx.x;
    int ww = bid & 15, head = (bid >> 4) & 7, b = bid >> 7;
    int win = b * 16 + ww;

    const char* Qp = (const char*)&g_half[0][(size_t)(win * 8 + head) * 256 * 40];
    const char* Kp = (const char*)&g_half[1][(size_t)(win * 8 + head) * 256 * 40];
    const char* Vp = (const char*)&g_half[2][(size_t)(win * 8 + head) * 256 * 40];

    // prologue: stage everything (Q, K, V = 1280 x 16B each), one wait.
#pragma unroll
    for (int it = 0; it < 5; it++) {
        int i = it * 256 + tid;
        cpa16(smb + QS + i * 16, Qp + i * 16);
        cpa16(smb + KS + i * 16, Kp + i * 16);
        cpa16(smb + VS + i * 16, Vp + i * 16);
    }
    for (int i = tid; i < 288; i += 256) cpa4(smb + WT + i * 4, gw + (head * 32 + (i & 31)) * 9 + (i >> 5));
    if (tid < 32) cpa4(smb + BSO + tid * 4, gb + head * 32 + tid);
    CPA_COMMIT();
    CPA_WAIT(0);
    __syncthreads();     // only block barrier in the kernel

    // hoisted Q fragments: [rb][kc][4]
    uint32_t qf[2][2][4];
#pragma unroll
    for (int rb = 0; rb < 2; rb++)
#pragma unroll
        for (int kc = 0; kc < 2; kc++) {
            uint32_t a = smb + QS
                + (uint32_t)(warp * 32 + rb * 16 + (lane & 7) + ((lane >> 3) & 1) * 8) * 80
                + (uint32_t)(kc * 16 + (lane >> 4) * 8) * 2;
            ldsm4(qf[rb][kc][0], qf[rb][kc][1], qf[rb][kc][2], qf[rb][kc][3], a);
        }

    float O[2][4][4];
#pragma unroll
    for (int rb = 0; rb < 2; rb++)
#pragma unroll
        for (int nj = 0; nj < 4; nj++) O[rb][nj][0] = O[rb][nj][1] = O[rb][nj][2] = O[rb][nj][3] = 0.f;
    float lr[2][2] = {{0.f, 0.f}, {0.f, 0.f}};

#pragma unroll
    for (int kb = 0; kb < 4; kb++) {
        int keyb = kb * 64;
        uint32_t ap[2][4][4];
#pragma unroll
        for (int rb = 0; rb < 2; rb++) {
#pragma unroll
            for (int j = 0; j < 8; j++) {
                uint32_t ka = smb + KS + (uint32_t)(keyb + j * 8 + (lane & 7)) * 80
                            + (uint32_t)((lane >> 3) * 8) * 2;
                uint32_t r0, r1, r2, r3;
                ldsm4(r0, r1, r2, r3, ka);
                float a4[4] = {0.f, 0.f, 0.f, 0.f};
                mma16816(a4, qf[rb][0], r0, r1);
                mma16816(a4, qf[rb][1], r2, r3);
                float e0 = __expf(a4[0]), e1 = __expf(a4[1]);
                float e2 = __expf(a4[2]), e3 = __expf(a4[3]);
                lr[rb][0] += e0 + e1;
                lr[rb][1] += e2 + e3;
                ap[rb][j >> 1][(j & 1) * 2]     = pkhf(e0, e1);
                ap[rb][j >> 1][(j & 1) * 2 + 1] = pkhf(e2, e3);
            }
        }
        // O += P V (V frags shared by both row blocks)
#pragma unroll
        for (int nj = 0; nj < 4; nj++) {
#pragma unroll
            for (int cp = 0; cp < 2; cp++) {
                uint32_t va = smb + VS + (uint32_t)(keyb + cp * 32 + lane) * 80 + (uint32_t)(nj * 8) * 2;
                uint32_t r0, r1, r2, r3;
                ldsm4t(r0, r1, r2, r3, va);
                mma16816(O[0][nj], ap[0][2 * cp],     r0, r1);
                mma16816(O[0][nj], ap[0][2 * cp + 1], r2, r3);
                mma16816(O[1][nj], ap[1][2 * cp],     r0, r1);
                mma16816(O[1][nj], ap[1][2 * cp + 1], r2, r3);
            }
        }
    }

    // epilogue: normalize + lepe (fp16 v), store windowed fp32
    size_t obase = (size_t)(win * 8 + head) * (256 * 32);
#pragma unroll
    for (int rb = 0; rb < 2; rb++) {
        float l0 = lr[rb][0], l1 = lr[rb][1];
        l0 += __shfl_xor_sync(0xffffffffu, l0, 1);
        l0 += __shfl_xor_sync(0xffffffffu, l0, 2);
        l1 += __shfl_xor_sync(0xffffffffu, l1, 1);
        l1 += __shfl_xor_sync(0xffffffffu, l1, 2);
        float inv0 = 1.0f / l0, inv1 = 1.0f / l1;
        int q0 = warp * 32 + rb * 16;
        int r = lane >> 2, cp2 = (lane & 3) * 2;
        int t0 = q0 + r, t1 = t0 + 8;
#pragma unroll
        for (int nj = 0; nj < 4; nj++) {
            int d = nj * 8 + cp2;
#pragma unroll
            for (int q = 0; q < 2; q++) {
                int t = q ? t1 : t0;
                int h = t >> 2, ws = t & 3;
                float ax = Bs[d], ay = Bs[d + 1];
#pragma unroll
                for (int kh = 0; kh < 3; kh++) {
                    int hn = h + kh - 1;
                    if ((unsigned)hn < 64u) {
#pragma unroll
                        for (int kw = 0; kw < 3; kw++) {
                            int wn = ws + kw - 1;
                            if ((unsigned)wn < 4u) {
                                int tn = hn * 4 + wn;
                                uint32_t vp = *(const uint32_t*)(sm8 + VS + tn * 80 + d * 2);
                                float vx = __half2float(__ushort_as_half((unsigned short)vp));
                                float vy = __half2float(__ushort_as_half((unsigned short)(vp >> 16)));
                                float2 wg = *(const float2*)(Wt + (kh * 3 + kw) * 32 + d);
                                ax = fmaf(vx, wg.x, ax);
                                ay = fmaf(vy, wg.y, ay);
                            }
                        }
                    }
                }
                float inv = q ? inv1 : inv0;
                float ox = O[rb][nj][q * 2], oy = O[rb][nj][q * 2 + 1];
                *(float2*)(g_oscr + obase + (size_t)t * 32 + d) =
                    make_float2(fmaf(ox, inv, ax), fmaf(oy, inv, ay));
            }
        }
    }
}

// Kernel 3: inverse repack g_oscr -> out (B,C,H,W).
__global__ void __launch_bounds__(256) unpack_kernel(float* __restrict__ out) {
    __shared__ float tile[64 * 33];
    int r = blockIdx.x;
    int h = r & 63; r >>= 6;
    int head = r & 7, b = r >> 3;
    int tid = threadIdx.x;
    int w = tid >> 2, c8 = (tid & 3) * 8;
    int ww = w & 15, wsp = w >> 4;
    int win = b * 16 + ww, t = h * 4 + wsp;
    const float* src = g_oscr + ((size_t)(win * 8 + head) * 256 + t) * 32 + c8;
    float4 a = ((const float4*)src)[0], bb = ((const float4*)src)[1];
    float vv[8] = {a.x, a.y, a.z, a.w, bb.x, bb.y, bb.z, bb.w};
#pragma unroll
    for (int j = 0; j < 8; j++) tile[w * 33 + c8 + j] = vv[j];
    __syncthreads();
    int c = tid >> 3, w0 = (tid & 7) * 8;
    float o[8];
#pragma unroll
    for (int j = 0; j < 8; j++) o[j] = tile[(w0 + j) * 33 + c];
    float* dst = out + ((size_t)(b * 256 + head * 32 + c)) * 4096 + h * 64 + w0;
    ((float4*)dst)[0] = make_float4(o[0], o[1], o[2], o[3]);
    ((float4*)dst)[1] = make_float4(o[4], o[5], o[6], o[7]);
}

extern "C" void kernel_launch(void* const* d_in, const int* in_sizes, int n_in,
                              void* d_out, int out_size) {
    const float* temp = (const float*)d_in[0];
    const float* gw = (const float*)d_in[1];
    const float* gb = (const float*)d_in[2];
    float* out = (float*)d_out;
    (void)in_sizes; (void)n_in; (void)out_size;

    cudaFuncSetAttribute(attn_mma, cudaFuncAttributeMaxDynamicSharedMemorySize, SMEM_SZ);
    repack_kernel<<<12288, 256>>>(temp);
    attn_mma<<<1024, 256, SMEM_SZ>>>(gw, gb);
    unpack_kernel<<<4096, 256>>>(out);
}

// round 14
// speedup vs baseline: 1.7558x; 1.0203x over previous
#include <cuda_runtime.h>
#include <cuda_fp16.h>
#include <cstdint>

namespace {
constexpr float SCALE = 0.17677669529663687f;                 // 32^-0.5
constexpr float LOG2E = 1.4426950408889634f;
// attn smem. fp16 rows: 40 elems = 80 B. 8-row ldmatrix sets at stride 80 B
// hit word offsets {0,20,8,28,16,4,24,12}*4B -> all 32 banks, 0 conflicts.
constexpr int QS  = 0;                    // [256][40] fp16 (cols 0-31 data)
constexpr int KS  = 20480;                // [256][40] fp16 (ALL of K resident)
constexpr int VS  = 40960;                // [256][40] fp16
constexpr int WT  = 61440;                // [9][32] fp32
constexpr int BSO = 62592;                // [32] fp32
constexpr int SMEM_SZ = 62720;
}

// fp16 windowed scratch, attn-smem-image layout: [s][((win*8+head)*256+t)*40]
__device__ __align__(16) unsigned short g_half[3][(size_t)262144 * 40];
__device__ float g_oscr[8388608];          // out windowed [win][head][t][d] fp32

__device__ __forceinline__ uint32_t pkhf(float lo, float hi) {
    uint32_t r;
    asm("cvt.rn.f16x2.f32 %0, %1, %2;" : "=r"(r) : "f"(hi), "f"(lo));
    return r;
}
__device__ __forceinline__ float ex2f(float x) {             // 2^x fp32 MUFU
    float r;
    asm("ex2.approx.f32 %0, %1;" : "=f"(r) : "f"(x));
    return r;
}
__device__ __forceinline__ void ldsm4(uint32_t& r0, uint32_t& r1, uint32_t& r2, uint32_t& r3, uint32_t a) {
    asm volatile("ldmatrix.sync.aligned.m8n8.x4.shared.b16 {%0,%1,%2,%3}, [%4];"
        : "=r"(r0), "=r"(r1), "=r"(r2), "=r"(r3) : "r"(a));
}
__device__ __forceinline__ void ldsm4t(uint32_t& r0, uint32_t& r1, uint32_t& r2, uint32_t& r3, uint32_t a) {
    asm volatile("ldmatrix.sync.aligned.m8n8.x4.trans.shared.b16 {%0,%1,%2,%3}, [%4];"
        : "=r"(r0), "=r"(r1), "=r"(r2), "=r"(r3) : "r"(a));
}
__device__ __forceinline__ void mma16816(float* d, const uint32_t* a, uint32_t b0, uint32_t b1) {
    asm volatile("mma.sync.aligned.m16n8k16.row.col.f32.f16.f16.f32 "
        "{%0,%1,%2,%3}, {%4,%5,%6,%7}, {%8,%9}, {%0,%1,%2,%3};"
        : "+f"(d[0]), "+f"(d[1]), "+f"(d[2]), "+f"(d[3])
        : "r"(a[0]), "r"(a[1]), "r"(a[2]), "r"(a[3]), "r"(b0), "r"(b1));
}
__device__ __forceinline__ void cpa16(uint32_t dst, const void* src) {
    asm volatile("cp.async.cg.shared.global [%0], [%1], 16;" :: "r"(dst), "l"(src));
}
__device__ __forceinline__ void cpa4(uint32_t dst, const void* src) {
    asm volatile("cp.async.ca.shared.global [%0], [%1], 4;" :: "r"(dst), "l"(src));
}
#define CPA_COMMIT() asm volatile("cp.async.commit_group;" ::: "memory")
#define CPA_WAIT(n)  asm volatile("cp.async.wait_group %0;" :: "n"(n) : "memory")

// ---------------------------------------------------------------------------
// Kernel 1: repack temp (B,3,C,H,W) fp32 -> fp16 windowed scratch.
// Q pre-scaled by 32^-0.5 * log2(e) (logits emerge in log2 domain).
// ---------------------------------------------------------------------------
__global__ void __launch_bounds__(256) repack_kernel(const float* __restrict__ temp) {
    __shared__ float tile[64 * 33];
    int r = blockIdx.x;
    int h = r & 63; r >>= 6;
    int head = r & 7; r >>= 3;
    int s = r % 3, b = r / 3;
    int tid = threadIdx.x;
    const float* src = temp + ((size_t)((b * 3 + s) * 256 + head * 32)) * 4096 + h * 64;
    int c = tid >> 3, w0 = (tid & 7) * 8;
    const float4* p = (const float4*)(src + (size_t)c * 4096 + w0);
    float4 v0 = p[0], v1 = p[1];
    float vv[8] = {v0.x, v0.y, v0.z, v0.w, v1.x, v1.y, v1.z, v1.w};
#pragma unroll
    for (int j = 0; j < 8; j++) tile[(w0 + j) * 33 + c] = vv[j];
    __syncthreads();
    int w = tid >> 2, c8 = (tid & 3) * 8;
    float o[8];
#pragma unroll
    for (int j = 0; j < 8; j++) o[j] = tile[w * 33 + c8 + j];
    int ww = w & 15, wsp = w >> 4;
    int win = b * 16 + ww, t = h * 4 + wsp;
    float m = (s == 0) ? SCALE * LOG2E : 1.0f;
    uint32_t pk[4];
#pragma unroll
    for (int j = 0; j < 4; j++) pk[j] = pkhf(o[2 * j] * m, o[2 * j + 1] * m);
    unsigned short* row = &g_half[s][((size_t)(win * 8 + head) * 256 + t) * 40];
    *(uint4*)(row + c8) = make_uint4(pk[0], pk[1], pk[2], pk[3]);
}

// ---------------------------------------------------------------------------
// Kernel 2: fp16 HMMA attention + lepe. CTA = (win,head), 256 thr / 8 warps,
// 2 CTAs/SM. All Q/K/V resident; exp = ex2.approx.f32 on fp32 accumulators
// (log2e pre-folded into Q); row sums in fp32 registers (R11-proven path);
// K frags shared across both row blocks.
// ---------------------------------------------------------------------------
__global__ void __launch_bounds__(256, 2) attn_mma(const float* __restrict__ gw,
                                                   const float* __restrict__ gb) {
    extern __shared__ char sm8[];
    uint32_t smb = (uint32_t)__cvta_generic_to_shared(sm8);
    float* Wt = (float*)(sm8 + WT);
    float* Bs = (float*)(sm8 + BSO);

    int tid = threadIdx.x, lane = tid & 31, warp = tid >> 5;
    int bid = blockIdx.x;
    int ww = bid & 15, head = (bid >> 4) & 7, b = bid >> 7;
    int win = b * 16 + ww;

    const char* Qp = (const char*)&g_half[0][(size_t)(win * 8 + head) * 256 * 40];
    const char* Kp = (const char*)&g_half[1][(size_t)(win * 8 + head) * 256 * 40];
    const char* Vp = (const char*)&g_half[2][(size_t)(win * 8 + head) * 256 * 40];

    // prologue: stage everything, one wait.
#pragma unroll
    for (int it = 0; it < 5; it++) {
        int i = it * 256 + tid;
        cpa16(smb + QS + i * 16, Qp + i * 16);
        cpa16(smb + KS + i * 16, Kp + i * 16);
        cpa16(smb + VS + i * 16, Vp + i * 16);
    }
    for (int i = tid; i < 288; i += 256) cpa4(smb + WT + i * 4, gw + (head * 32 + (i & 31)) * 9 + (i >> 5));
    if (tid < 32) cpa4(smb + BSO + tid * 4, gb + head * 32 + tid);
    CPA_COMMIT();
    CPA_WAIT(0);
    __syncthreads();     // only block barrier in the kernel

    // hoisted Q fragments: [rb][kc][4]
    uint32_t qf[2][2][4];
#pragma unroll
    for (int rb = 0; rb < 2; rb++)
#pragma unroll
        for (int kc = 0; kc < 2; kc++) {
            uint32_t a = smb + QS
                + (uint32_t)(warp * 32 + rb * 16 + (lane & 7) + ((lane >> 3) & 1) * 8) * 80
                + (uint32_t)(kc * 16 + (lane >> 4) * 8) * 2;
            ldsm4(qf[rb][kc][0], qf[rb][kc][1], qf[rb][kc][2], qf[rb][kc][3], a);
        }

    float O[2][4][4];
#pragma unroll
    for (int rb = 0; rb < 2; rb++)
#pragma unroll
        for (int nj = 0; nj < 4; nj++) O[rb][nj][0] = O[rb][nj][1] = O[rb][nj][2] = O[rb][nj][3] = 0.f;
    float lr[2][2] = {{0.f, 0.f}, {0.f, 0.f}};

#pragma unroll
    for (int kb = 0; kb < 4; kb++) {
        int keyb = kb * 64;
        uint32_t ap[2][4][4];
#pragma unroll
        for (int j = 0; j < 8; j++) {
            uint32_t ka = smb + KS + (uint32_t)(keyb + j * 8 + (lane & 7)) * 80
                        + (uint32_t)((lane >> 3) * 8) * 2;
            uint32_t r0, r1, r2, r3;
            ldsm4(r0, r1, r2, r3, ka);       // K frags shared by both rb
#pragma unroll
            for (int rb = 0; rb < 2; rb++) {
                float a4[4] = {0.f, 0.f, 0.f, 0.f};
                mma16816(a4, qf[rb][0], r0, r1);
                mma16816(a4, qf[rb][1], r2, r3);
                // a4 = s*log2e (fp32). Exponentiate in fp32, THEN pack fp16.
                float e0 = ex2f(a4[0]), e1 = ex2f(a4[1]);
                float e2 = ex2f(a4[2]), e3 = ex2f(a4[3]);
                lr[rb][0] += e0 + e1;
                lr[rb][1] += e2 + e3;
                ap[rb][j >> 1][(j & 1) * 2]     = pkhf(e0, e1);
                ap[rb][j >> 1][(j & 1) * 2 + 1] = pkhf(e2, e3);
            }
        }
        // O += P V (V frags shared by both row blocks)
#pragma unroll
        for (int nj = 0; nj < 4; nj++) {
#pragma unroll
            for (int cp = 0; cp < 2; cp++) {
                uint32_t va = smb + VS + (uint32_t)(keyb + cp * 32 + lane) * 80 + (uint32_t)(nj * 8) * 2;
                uint32_t r0, r1, r2, r3;
                ldsm4t(r0, r1, r2, r3, va);
                mma16816(O[0][nj], ap[0][2 * cp],     r0, r1);
                mma16816(O[0][nj], ap[0][2 * cp + 1], r2, r3);
                mma16816(O[1][nj], ap[1][2 * cp],     r0, r1);
                mma16816(O[1][nj], ap[1][2 * cp + 1], r2, r3);
            }
        }
    }

    // epilogue: normalize + lepe (fp16 v), store windowed fp32
    size_t obase = (size_t)(win * 8 + head) * (256 * 32);
#pragma unroll
    for (int rb = 0; rb < 2; rb++) {
        float l0 = lr[rb][0], l1 = lr[rb][1];
        l0 += __shfl_xor_sync(0xffffffffu, l0, 1);
        l0 += __shfl_xor_sync(0xffffffffu, l0, 2);
        l1 += __shfl_xor_sync(0xffffffffu, l1, 1);
        l1 += __shfl_xor_sync(0xffffffffu, l1, 2);
        float inv0 = 1.0f / l0, inv1 = 1.0f / l1;
        int q0 = warp * 32 + rb * 16;
        int r = lane >> 2, cp2 = (lane & 3) * 2;
        int t0 = q0 + r, t1 = t0 + 8;
#pragma unroll
        for (int nj = 0; nj < 4; nj++) {
            int d = nj * 8 + cp2;
#pragma unroll
            for (int q = 0; q < 2; q++) {
                int t = q ? t1 : t0;
                int h = t >> 2, ws = t & 3;
                float ax = Bs[d], ay = Bs[d + 1];
#pragma unroll
                for (int kh = 0; kh < 3; kh++) {
                    int hn = h + kh - 1;
                    if ((unsigned)hn < 64u) {
#pragma unroll
                        for (int kw = 0; kw < 3; kw++) {
                            int wn = ws + kw - 1;
                            if ((unsigned)wn < 4u) {
                                int tn = hn * 4 + wn;
                                uint32_t vp = *(const uint32_t*)(sm8 + VS + tn * 80 + d * 2);
                                float vx = __half2float(__ushort_as_half((unsigned short)vp));
                                float vy = __half2float(__ushort_as_half((unsigned short)(vp >> 16)));
                                float2 wg = *(const float2*)(Wt + (kh * 3 + kw) * 32 + d);
                                ax = fmaf(vx, wg.x, ax);
                                ay = fmaf(vy, wg.y, ay);
                            }
                        }
                    }
                }
                float inv = q ? inv1 : inv0;
                float ox = O[rb][nj][q * 2], oy = O[rb][nj][q * 2 + 1];
                *(float2*)(g_oscr + obase + (size_t)t * 32 + d) =
                    make_float2(fmaf(ox, inv, ax), fmaf(oy, inv, ay));
            }
        }
    }
}

// Kernel 3: inverse repack g_oscr -> out (B,C,H,W).
__global__ void __launch_bounds__(256) unpack_kernel(float* __restrict__ out) {
    __shared__ float tile[64 * 33];
    int r = blockIdx.x;
    int h = r & 63; r >>= 6;
    int head = r & 7, b = r >> 3;
    int tid = threadIdx.x;
    int w = tid >> 2, c8 = (tid & 3) * 8;
    int ww = w & 15, wsp = w >> 4;
    int win = b * 16 + ww, t = h * 4 + wsp;
    const float* src = g_oscr + ((size_t)(win * 8 + head) * 256 + t) * 32 + c8;
    float4 a = ((const float4*)src)[0], bb = ((const float4*)src)[1];
    float vv[8] = {a.x, a.y, a.z, a.w, bb.x, bb.y, bb.z, bb.w};
#pragma unroll
    for (int j = 0; j < 8; j++) tile[w * 33 + c8 + j] = vv[j];
    __syncthreads();
    int c = tid >> 3, w0 = (tid & 7) * 8;
    float o[8];
#pragma unroll
    for (int j = 0; j < 8; j++) o[j] = tile[(w0 + j) * 33 + c];
    float* dst = out + ((size_t)(b * 256 + head * 32 + c)) * 4096 + h * 64 + w0;
    ((float4*)dst)[0] = make_float4(o[0], o[1], o[2], o[3]);
    ((float4*)dst)[1] = make_float4(o[4], o[5], o[6], o[7]);
}

extern "C" void kernel_launch(void* const* d_in, const int* in_sizes, int n_in,
                              void* d_out, int out_size) {
    const float* temp = (const float*)d_in[0];
    const float* gw = (const float*)d_in[1];
    const float* gb = (const float*)d_in[2];
    float* out = (float*)d_out;
    (void)in_sizes; (void)n_in; (void)out_size;

    cudaFuncSetAttribute(attn_mma, cudaFuncAttributeMaxDynamicSharedMemorySize, SMEM_SZ);
    repack_kernel<<<12288, 256>>>(temp);
    attn_mma<<<1024, 256, SMEM_SZ>>>(gw, gb);
    unpack_kernel<<<4096, 256>>>(out);
}